// round 7
// baseline (speedup 1.0000x reference)
#include <cuda_runtime.h>
#include <math.h>

#define DTc 1e-4f
#define LN_EPS 1e-5f
#define B_ 16
#define S_ 4096
#define D_ 256
#define N_ 16
#define CHUNK 64
#define NCHUNK (S_/CHUNK)   // 64
#define PADX 36             // 32 k-cols + 4 pad

// scratch (no cudaMalloc allowed)
__device__ float g_H[B_*S_*N_];          // 4 MB

typedef unsigned long long ull;

__device__ __forceinline__ void fma2(ull& d, ull a, ull b){
    asm("fma.rn.f32x2 %0, %1, %2, %0;" : "+l"(d) : "l"(a), "l"(b));
}
__device__ __forceinline__ ull mul2(ull a, ull b){
    ull r;
    asm("mul.rn.f32x2 %0, %1, %2;" : "=l"(r) : "l"(a), "l"(b));
    return r;
}
__device__ __forceinline__ ull pack2(float v){
    ull r;
    asm("mov.b64 %0, {%1, %1};" : "=l"(r) : "f"(v));
    return r;
}
__device__ __forceinline__ void unpk(float& lo, float& hi, ull v){
    asm("mov.b64 {%0, %1}, %2;" : "=f"(lo), "=f"(hi) : "l"(v));
}
__device__ __forceinline__ void cpa16(float* s, const float4* g){
    unsigned sa = (unsigned)__cvta_generic_to_shared(s);
    asm volatile("cp.async.ca.shared.global [%0], [%1], 16;" :: "r"(sa), "l"(g));
}

// ---------------------------------------------------------------------------
// K1: U = DT * x @ Bm^T for 256 rows (4 chunks). FFMA2 over k-parity pairs,
// cp.async double-buffered 32-col k-tiles, per-chunk local scans (h0=0).
// (unchanged from round 6)
// ---------------------------------------------------------------------------
__global__ void __launch_bounds__(256,2) k1(const float* __restrict__ x,
                                            const float* __restrict__ A,
                                            const float* __restrict__ Bm){
    extern __shared__ float sm[];
    float* sx0 = sm;                       // 256*36
    float* sx1 = sm + 256*PADX;            // 256*36
    float* sw2 = sm + 2*256*PADX;          // [n][k] pad 260: 16*260
    float* su  = sw2 + 16*260;             // [row][n] pad 20: 256*20
    const int blk = blockIdx.x, b = blockIdx.y;
    const int tid = threadIdx.x;
    const int nt = tid & 3, tt = tid >> 2; // tt 0..63

    for (int i = tid; i < N_*D_; i += 256){
        int nn = i >> 8, k = i & 255;
        sw2[nn*260 + k] = DTc * Bm[i];
    }

    const float4* xg = (const float4*)(x + (size_t)(b*S_ + blk*256)*D_);

    ull acc[4][4];
    #pragma unroll
    for (int r = 0; r < 4; r++)
        #pragma unroll
        for (int i = 0; i < 4; i++) acc[r][i] = 0ull;

    #pragma unroll
    for (int j = 0; j < 8; j++){
        int i = tid + j*256;
        int t = i >> 3, q = i & 7;
        cpa16(sx0 + t*PADX + q*4, xg + (size_t)t*64 + q);
    }
    asm volatile("cp.async.commit_group;");

    #pragma unroll
    for (int kt = 0; kt < 8; kt++){
        float* cur = (kt & 1) ? sx1 : sx0;
        float* nxt = (kt & 1) ? sx0 : sx1;
        if (kt < 7){
            #pragma unroll
            for (int j = 0; j < 8; j++){
                int i = tid + j*256;
                int t = i >> 3, q = i & 7;
                cpa16(nxt + t*PADX + q*4, xg + (size_t)t*64 + (kt+1)*8 + q);
            }
            asm volatile("cp.async.commit_group;");
            asm volatile("cp.async.wait_group 1;");
        } else {
            asm volatile("cp.async.wait_group 0;");
        }
        __syncthreads();

        const ulonglong2* xr0 = (const ulonglong2*)(cur + (tt      )*PADX);
        const ulonglong2* xr1 = (const ulonglong2*)(cur + (tt +  64)*PADX);
        const ulonglong2* xr2 = (const ulonglong2*)(cur + (tt + 128)*PADX);
        const ulonglong2* xr3 = (const ulonglong2*)(cur + (tt + 192)*PADX);
        const ulonglong2* wr0 = (const ulonglong2*)(sw2 + (nt     )*260 + kt*32);
        const ulonglong2* wr1 = (const ulonglong2*)(sw2 + (nt +  4)*260 + kt*32);
        const ulonglong2* wr2 = (const ulonglong2*)(sw2 + (nt +  8)*260 + kt*32);
        const ulonglong2* wr3 = (const ulonglong2*)(sw2 + (nt + 12)*260 + kt*32);

        #pragma unroll
        for (int k4 = 0; k4 < 8; k4++){
            ulonglong2 xa = xr0[k4], xb = xr1[k4], xc = xr2[k4], xd = xr3[k4];
            ulonglong2 w0 = wr0[k4], w1 = wr1[k4], w2 = wr2[k4], w3 = wr3[k4];
            fma2(acc[0][0], xa.x, w0.x); fma2(acc[0][0], xa.y, w0.y);
            fma2(acc[0][1], xa.x, w1.x); fma2(acc[0][1], xa.y, w1.y);
            fma2(acc[0][2], xa.x, w2.x); fma2(acc[0][2], xa.y, w2.y);
            fma2(acc[0][3], xa.x, w3.x); fma2(acc[0][3], xa.y, w3.y);
            fma2(acc[1][0], xb.x, w0.x); fma2(acc[1][0], xb.y, w0.y);
            fma2(acc[1][1], xb.x, w1.x); fma2(acc[1][1], xb.y, w1.y);
            fma2(acc[1][2], xb.x, w2.x); fma2(acc[1][2], xb.y, w2.y);
            fma2(acc[1][3], xb.x, w3.x); fma2(acc[1][3], xb.y, w3.y);
            fma2(acc[2][0], xc.x, w0.x); fma2(acc[2][0], xc.y, w0.y);
            fma2(acc[2][1], xc.x, w1.x); fma2(acc[2][1], xc.y, w1.y);
            fma2(acc[2][2], xc.x, w2.x); fma2(acc[2][2], xc.y, w2.y);
            fma2(acc[2][3], xc.x, w3.x); fma2(acc[2][3], xc.y, w3.y);
            fma2(acc[3][0], xd.x, w0.x); fma2(acc[3][0], xd.y, w0.y);
            fma2(acc[3][1], xd.x, w1.x); fma2(acc[3][1], xd.y, w1.y);
            fma2(acc[3][2], xd.x, w2.x); fma2(acc[3][2], xd.y, w2.y);
            fma2(acc[3][3], xd.x, w3.x); fma2(acc[3][3], xd.y, w3.y);
        }
        __syncthreads();
    }

    #pragma unroll
    for (int r = 0; r < 4; r++)
        #pragma unroll
        for (int i = 0; i < 4; i++){
            float lo, hi;
            unpk(lo, hi, acc[r][i]);
            su[(tt + 64*r)*20 + (nt + 4*i)] = lo + hi;
        }
    __syncthreads();

    if (tid < 64){
        int n = tid & 15, cc = tid >> 4;
        float a = expf(-DTc*fabsf(A[n]));
        float h = 0.f;
        float* p = su + cc*64*20 + n;
        #pragma unroll 8
        for (int t = 0; t < CHUNK; t++){
            h = fmaf(a, h, p[t*20]);
            p[t*20] = h;
        }
    }
    __syncthreads();

    float* Hg = g_H + (size_t)(b*S_ + blk*256)*N_;
    #pragma unroll
    for (int j = 0; j < 16; j++){
        int i = tid + j*256;
        Hg[i] = su[(i>>4)*20 + (i&15)];
    }
}

// ---------------------------------------------------------------------------
// K3: block = 128 rows (2 chunks), 256 thr = 8 warps; warp owns 16 rows,
// processed in 2 passes of 8. h stored DUPLICATED (ull pairs) in smem so the
// GEMM inner loop has zero pack ops: per n = 4 bcast LDS.128 + 2 LDS.128 C
// + 32 FFMA2. In-block carry (threads 0..15), fixup, fused LayerNorm.
// ---------------------------------------------------------------------------
__global__ void __launch_bounds__(256,2) k3(const float* __restrict__ x,
                                            const float* __restrict__ A,
                                            const float* __restrict__ Cm,
                                            const float* __restrict__ Dv,
                                            const float* __restrict__ gamma,
                                            const float* __restrict__ beta,
                                            float* __restrict__ out){
    __shared__ __align__(16) float sC[N_*260];     // [n][d] pad 260
    __shared__ __align__(16) ull   shd[N_*132];    // [n][t] dup pairs, pad 132
    __shared__ __align__(16) float sDv[D_], sg[D_], sb[D_];
    __shared__ float scarr[2*N_];                  // carry per chunk
    const int blk = blockIdx.x, b = blockIdx.y;    // blk over 32 (128 rows each)
    const int tid = threadIdx.x;
    const int warp = tid >> 5, lane = tid & 31;
    const int row0 = blk*128;
    const int cb = 2*blk;                          // first chunk index

    // in-block carry for chunk cb (threads 0..15), then chunk cb+1
    if (tid < 16){
        const int n = tid;
        float a = expf(-DTc*fabsf(A[n]));
        float a2=a*a, a4=a2*a2, a8=a4*a4, a16=a8*a8, a32=a16*a16, a64=a32*a32;
        float carry = 0.f;
        for (int c0 = 0; c0 < cb; c0 += 16){
            float v[16];
            #pragma unroll
            for (int i = 0; i < 16; i++)
                if (c0 + i < cb)
                    v[i] = g_H[((size_t)b*S_ + (c0+i)*CHUNK + (CHUNK-1))*N_ + n];
            #pragma unroll
            for (int i = 0; i < 16; i++)
                if (c0 + i < cb)
                    carry = fmaf(a64, carry, v[i]);
        }
        scarr[n] = carry;
        float L0 = g_H[((size_t)b*S_ + cb*CHUNK + (CHUNK-1))*N_ + n];
        scarr[16 + n] = fmaf(a64, carry, L0);
    }

    // stage C (transposed), Dv/gamma/beta, and h (duplicated pairs)
    for (int i = tid; i < D_*N_; i += 256){
        int d = i >> 4, n = i & 15;
        sC[n*260 + d] = Cm[i];
    }
    for (int i = tid; i < D_; i += 256){ sDv[i]=Dv[i]; sg[i]=gamma[i]; sb[i]=beta[i]; }
    {
        const float* Hg = g_H + (size_t)(b*S_ + row0)*N_;
        #pragma unroll
        for (int j = 0; j < 8; j++){
            int i = tid + j*256;            // 2048 elems
            int t = i >> 4, n = i & 15;
            shd[n*132 + t] = pack2(Hg[i]);
        }
    }
    __syncthreads();

    // fixup: 64 threads, (n, seg of 32 rows): h += a^{t_local+1} * carry_chunk
    if (tid < 64){
        int n = tid & 15, seg = tid >> 4;   // seg 0..3
        float absA = fabsf(A[n]);
        float a = expf(-DTc*absA);
        float carry = scarr[(seg >> 1)*16 + n];
        float p = carry * expf(-DTc*absA*(float)((seg & 1)*32));
        ull* rowp = shd + n*132 + seg*32;
        #pragma unroll
        for (int i = 0; i < 32; i++){
            p *= a;
            float lo, hi;
            unpk(lo, hi, rowp[i]);
            rowp[i] = pack2(lo + p);
        }
    }
    __syncthreads();

    // GEMM + LN: warp owns rows warp*16 .. +15, two passes of 8
    #pragma unroll
    for (int pass = 0; pass < 2; pass++){
        const int t0 = warp*16 + pass*8;
        const float* xr = x + (size_t)(b*S_ + row0 + t0)*D_;
        const int d0 = 4*lane;

        ull y2[8][2][2];
        #pragma unroll
        for (int r = 0; r < 8; r++){
            #pragma unroll
            for (int j = 0; j < 2; j++){
                int d = d0 + 128*j;
                float4 xv = *(const float4*)(xr + r*D_ + d);
                ulonglong2 xp = *(ulonglong2*)&xv;
                ulonglong2 dv = *(const ulonglong2*)(sDv + d);
                y2[r][j][0] = mul2(xp.x, dv.x);
                y2[r][j][1] = mul2(xp.y, dv.y);
            }
        }

        #pragma unroll
        for (int n = 0; n < 16; n++){
            const ull* hp = shd + n*132 + t0;
            ulonglong2 h01 = *(const ulonglong2*)(hp    );
            ulonglong2 h23 = *(const ulonglong2*)(hp + 2);
            ulonglong2 h45 = *(const ulonglong2*)(hp + 4);
            ulonglong2 h67 = *(const ulonglong2*)(hp + 6);
            ulonglong2 c0 = *(const ulonglong2*)(sC + n*260 + d0);
            ulonglong2 c1 = *(const ulonglong2*)(sC + n*260 + d0 + 128);
            fma2(y2[0][0][0], h01.x, c0.x); fma2(y2[0][0][1], h01.x, c0.y);
            fma2(y2[0][1][0], h01.x, c1.x); fma2(y2[0][1][1], h01.x, c1.y);
            fma2(y2[1][0][0], h01.y, c0.x); fma2(y2[1][0][1], h01.y, c0.y);
            fma2(y2[1][1][0], h01.y, c1.x); fma2(y2[1][1][1], h01.y, c1.y);
            fma2(y2[2][0][0], h23.x, c0.x); fma2(y2[2][0][1], h23.x, c0.y);
            fma2(y2[2][1][0], h23.x, c1.x); fma2(y2[2][1][1], h23.x, c1.y);
            fma2(y2[3][0][0], h23.y, c0.x); fma2(y2[3][0][1], h23.y, c0.y);
            fma2(y2[3][1][0], h23.y, c1.x); fma2(y2[3][1][1], h23.y, c1.y);
            fma2(y2[4][0][0], h45.x, c0.x); fma2(y2[4][0][1], h45.x, c0.y);
            fma2(y2[4][1][0], h45.x, c1.x); fma2(y2[4][1][1], h45.x, c1.y);
            fma2(y2[5][0][0], h45.y, c0.x); fma2(y2[5][0][1], h45.y, c0.y);
            fma2(y2[5][1][0], h45.y, c1.x); fma2(y2[5][1][1], h45.y, c1.y);
            fma2(y2[6][0][0], h67.x, c0.x); fma2(y2[6][0][1], h67.x, c0.y);
            fma2(y2[6][1][0], h67.x, c1.x); fma2(y2[6][1][1], h67.x, c1.y);
            fma2(y2[7][0][0], h67.y, c0.x); fma2(y2[7][0][1], h67.y, c0.y);
            fma2(y2[7][1][0], h67.y, c1.x); fma2(y2[7][1][1], h67.y, c1.y);
        }

        float* og = out + (size_t)(b*S_ + row0 + t0)*D_;
        #pragma unroll
        for (int r = 0; r < 8; r++){
            float yv[8];
            float s = 0.f, s2 = 0.f;
            #pragma unroll
            for (int j = 0; j < 2; j++)
                #pragma unroll
                for (int p2 = 0; p2 < 2; p2++){
                    float lo, hi;
                    unpk(lo, hi, y2[r][j][p2]);
                    lo = fminf(fmaxf(lo, -10.f), 10.f);
                    hi = fminf(fmaxf(hi, -10.f), 10.f);
                    yv[j*4 + p2*2]     = lo;
                    yv[j*4 + p2*2 + 1] = hi;
                    s += lo + hi;
                    s2 = fmaf(lo, lo, s2);
                    s2 = fmaf(hi, hi, s2);
                }
            #pragma unroll
            for (int o = 16; o; o >>= 1){
                s  += __shfl_xor_sync(0xffffffffu, s,  o);
                s2 += __shfl_xor_sync(0xffffffffu, s2, o);
            }
            float mu   = s * (1.f/256.f);
            float var  = fmaf(s2, 1.f/256.f, -mu*mu);
            float rinv = rsqrtf(var + LN_EPS);
            #pragma unroll
            for (int j = 0; j < 2; j++){
                int d = d0 + 128*j;
                float4 gg = *(const float4*)(sg + d);
                float4 bb = *(const float4*)(sb + d);
                float4 o4;
                o4.x = fmaf((yv[j*4+0]-mu)*rinv, gg.x, bb.x);
                o4.y = fmaf((yv[j*4+1]-mu)*rinv, gg.y, bb.y);
                o4.z = fmaf((yv[j*4+2]-mu)*rinv, gg.z, bb.z);
                o4.w = fmaf((yv[j*4+3]-mu)*rinv, gg.w, bb.w);
                *(float4*)(og + r*D_ + d) = o4;
            }
        }
    }
}

// ---------------------------------------------------------------------------
extern "C" void kernel_launch(void* const* d_in, const int* in_sizes, int n_in,
                              void* d_out, int out_size){
    const float* x     = (const float*)d_in[0];
    const float* A     = (const float*)d_in[1];
    const float* Bm    = (const float*)d_in[2];
    const float* Cm    = (const float*)d_in[3];
    const float* Dv    = (const float*)d_in[4];
    const float* gamma = (const float*)d_in[5];
    const float* beta  = (const float*)d_in[6];
    float* out = (float*)d_out;

    size_t smem1 = (size_t)(2*256*PADX + 16*260 + 256*20) * sizeof(float); // 110848 B
    cudaFuncSetAttribute(k1, cudaFuncAttributeMaxDynamicSharedMemorySize, (int)smem1);

    dim3 grid1(S_/256, B_);     // 16 x 16 = 256 blocks
    dim3 grid3(S_/128, B_);     // 32 x 16 = 512 blocks
    k1<<<grid1, 256, smem1>>>(x, A, Bm);
    k3<<<grid3, 256>>>(x, A, Cm, Dv, gamma, beta, out);
}

// round 13
// speedup vs baseline: 1.4864x; 1.4864x over previous
#include <cuda_runtime.h>
#include <math.h>

#define DTc 1e-4f
#define LN_EPS 1e-5f
#define B_ 16
#define S_ 4096
#define D_ 256
#define N_ 16
#define CHUNK 64
#define NCHUNK (S_/CHUNK)   // 64
#define PADX 20             // 16 k-cols + 4 pad

// scratch (no cudaMalloc) — only chunk-boundary states cross blocks
__device__ float g_last[B_*NCHUNK*N_];   // 64 KB
__device__ unsigned g_barA;              // monotonic arrival counter (replay-safe)

typedef unsigned long long ull;

__device__ __forceinline__ void fma2(ull& d, ull a, ull b){
    asm("fma.rn.f32x2 %0, %1, %2, %0;" : "+l"(d) : "l"(a), "l"(b));
}
__device__ __forceinline__ ull mul2(ull a, ull b){
    ull r; asm("mul.rn.f32x2 %0, %1, %2;" : "=l"(r) : "l"(a), "l"(b)); return r;
}
__device__ __forceinline__ ull pack2(float v){
    ull r; asm("mov.b64 %0, {%1, %1};" : "=l"(r) : "f"(v)); return r;
}
__device__ __forceinline__ void unpk(float& lo, float& hi, ull v){
    asm("mov.b64 {%0, %1}, %2;" : "=f"(lo), "=f"(hi) : "l"(v));
}
__device__ __forceinline__ void cpa16(float* s, const float4* g){
    unsigned sa = (unsigned)__cvta_generic_to_shared(s);
    asm volatile("cp.async.ca.shared.global [%0], [%1], 16;" :: "r"(sa), "l"(g));
}

// ---------------------------------------------------------------------------
// Fused kernel: block = 256 rows (4 chunks) of one batch. 256 threads.
// Phase 1: U = DT*x@Bm^T (FFMA2, cp.async dbuf, 16-col tiles processed in two
//          8-col halves), local scans -> su (smem), chunk-lasts -> g_last.
//          Device-wide monotonic barrier (all 256 blocks co-resident at occ 2).
// Phase 2: carries from g_last, fixup h, y = h@Cm^T + x*Dv, clip, LayerNorm.
// ---------------------------------------------------------------------------
__global__ void __launch_bounds__(256,2) fused(const float* __restrict__ x,
                                               const float* __restrict__ A,
                                               const float* __restrict__ Bm,
                                               const float* __restrict__ Cm,
                                               const float* __restrict__ Dv,
                                               const float* __restrict__ gamma,
                                               const float* __restrict__ beta,
                                               float* __restrict__ out){
    extern __shared__ float sm[];
    float* sx0 = sm;                 // 256*20
    float* sx1 = sm + 5120;          // 256*20
    float* sw2 = sm + 10240;         // [n][k] pad 260 -> 4160
    float* su  = sm + 14400;         // [row][n] pad 20 -> 5120
    // phase-2 aliases
    float* sC  = sm;                 // [n][d] pad 260 -> 4160
    float* sDv = sm + 4160;
    float* sg  = sm + 4416;
    float* sb  = sm + 4672;          // ends 4928 < 5120
    float* shn = sm + 10240;         // [n][t] pad 260 -> 4160 (over sw2)
    __shared__ float scarr[4][N_];

    const int blk = blockIdx.x, b = blockIdx.y;   // 16 x 16 = 256 blocks
    const int tid = threadIdx.x;
    const int nt = tid & 3, tt = tid >> 2;        // tt 0..63
    const int cb = 4*blk;

    // ---- Phase 1: stage W ----
    for (int i = tid; i < N_*D_; i += 256){
        int nn = i >> 8, k = i & 255;
        sw2[nn*260 + k] = DTc * Bm[i];
    }

    const float4* xg = (const float4*)(x + (size_t)(b*S_ + blk*256)*D_);

    ull acc[4][4];
    #pragma unroll
    for (int r = 0; r < 4; r++)
        #pragma unroll
        for (int i = 0; i < 4; i++) acc[r][i] = 0ull;

    // preload k-tile 0 (16 cols = 4 float4 per row)
    #pragma unroll
    for (int j = 0; j < 4; j++){
        int i = tid + j*256;
        int t = i >> 2, q = i & 3;
        cpa16(sx0 + t*PADX + q*4, xg + (size_t)t*64 + q);
    }
    asm volatile("cp.async.commit_group;");

    float* cur = sx0; float* nxt = sx1;
    #pragma unroll 1
    for (int kt = 0; kt < 16; kt++){
        if (kt < 15){
            #pragma unroll
            for (int j = 0; j < 4; j++){
                int i = tid + j*256;
                int t = i >> 2, q = i & 3;
                cpa16(nxt + t*PADX + q*4, xg + (size_t)t*64 + (kt+1)*4 + q);
            }
            asm volatile("cp.async.commit_group;");
            asm volatile("cp.async.wait_group 1;");
        } else {
            asm volatile("cp.async.wait_group 0;");
        }
        __syncthreads();

        // two 8-col halves cover the full 16-col tile
        #pragma unroll
        for (int half = 0; half < 2; half++){
            ulonglong2 wv[4][2];
            #pragma unroll
            for (int i = 0; i < 4; i++){
                const ulonglong2* wp = (const ulonglong2*)(sw2 + (nt + 4*i)*260 + kt*16 + half*8);
                wv[i][0] = wp[0]; wv[i][1] = wp[1];
            }
            #pragma unroll
            for (int r = 0; r < 4; r++){
                const ulonglong2* xp = (const ulonglong2*)(cur + (tt + 64*r)*PADX + half*8);
                ulonglong2 x0 = xp[0], x1 = xp[1];
                #pragma unroll
                for (int i = 0; i < 4; i++){
                    fma2(acc[r][i], x0.x, wv[i][0].x);
                    fma2(acc[r][i], x0.y, wv[i][0].y);
                    fma2(acc[r][i], x1.x, wv[i][1].x);
                    fma2(acc[r][i], x1.y, wv[i][1].y);
                }
            }
        }
        __syncthreads();
        float* t2 = cur; cur = nxt; nxt = t2;
    }

    // acc -> su  (su[row][n], pad 20)
    #pragma unroll
    for (int r = 0; r < 4; r++)
        #pragma unroll
        for (int i = 0; i < 4; i++){
            float lo, hi;
            unpk(lo, hi, acc[r][i]);
            su[(tt + 64*r)*20 + (nt + 4*i)] = lo + hi;
        }
    __syncthreads();

    // local scans (64 chains) + chunk-last publish
    if (tid < 64){
        int n = tid & 15, cc = tid >> 4;
        float a = expf(-DTc*fabsf(A[n]));
        float h = 0.f;
        float* p = su + cc*64*20 + n;
        #pragma unroll 8
        for (int t = 0; t < CHUNK; t++){
            h = fmaf(a, h, p[t*20]);
            p[t*20] = h;
        }
        g_last[(b*NCHUNK + cb + cc)*N_ + n] = h;
    }
    __syncthreads();
    __threadfence();

    // ---- arrive (monotonic barrier) ----
    if (tid == 0)
        atomicAdd(&g_barA, 1u);

    // ---- staging for phase 2 (overlaps other blocks' phase 1) ----
    for (int i = tid; i < D_*N_; i += 256){
        int d = i >> 4, n = i & 15;
        sC[n*260 + d] = Cm[i];              // Cm[d][n] -> sC[n][d]
    }
    for (int i = tid; i < D_; i += 256){ sDv[i]=Dv[i]; sg[i]=gamma[i]; sb[i]=beta[i]; }
    // transpose su[t][n] -> shn[n][t]  (sw2 region, free now)
    #pragma unroll
    for (int j = 0; j < 16; j++){
        int i = tid + j*256;                // 4096
        int t = i >> 4, n = i & 15;
        shn[n*260 + t] = su[t*20 + n];
    }

    // ---- spin until all 256 blocks of this launch arrived ----
    if (tid == 0){
        unsigned snap = atomicAdd(&g_barA, 0u);           // >= our arrival
        unsigned target = ((snap - 1u) & ~255u) + 256u;   // launch base + 256
        unsigned v = snap;
        while (v < target){
            __nanosleep(64);
            asm volatile("ld.acquire.gpu.u32 %0, [%1];" : "=r"(v) : "l"(&g_barA));
        }
    }
    __syncthreads();
    __threadfence();

    // ---- carries for this block's 4 chunks ----
    if (tid < 16){
        const int n = tid;
        float a64 = expf(-DTc*fabsf(A[n])*64.f);
        float carry = 0.f;
        for (int c0 = 0; c0 < cb; c0 += 16){
            float v[16];
            #pragma unroll
            for (int i = 0; i < 16; i++)
                if (c0 + i < cb) v[i] = g_last[(b*NCHUNK + c0 + i)*N_ + n];
            #pragma unroll
            for (int i = 0; i < 16; i++)
                if (c0 + i < cb) carry = fmaf(a64, carry, v[i]);
        }
        scarr[0][n] = carry;
        #pragma unroll
        for (int cc = 1; cc < 4; cc++){
            carry = fmaf(a64, carry, g_last[(b*NCHUNK + cb + cc - 1)*N_ + n]);
            scarr[cc][n] = carry;
        }
    }
    __syncthreads();

    // ---- fixup: shn[n][t] += a^{tl+1} * carry_chunk ----
    {
        int n = tid & 15, seg = tid >> 4;   // seg 0..15, 16 rows each
        int cc = seg >> 2;
        int tl0 = (seg & 3)*16;
        float absA = fabsf(A[n]);
        float a = expf(-DTc*absA);
        float p = scarr[cc][n] * expf(-DTc*absA*(float)tl0);
        float* row = shn + n*260 + seg*16;
        #pragma unroll
        for (int i = 0; i < 16; i++){
            p *= a;
            row[i] += p;
        }
    }
    __syncthreads();

    // ---- Phase 2: GEMM + LN. 8 warps x 32 rows, 8 passes of 4 rows ----
    const int warp = tid >> 5, lane = tid & 31;
    const int d0 = 4*lane;

    #pragma unroll 1
    for (int pass = 0; pass < 8; pass++){
        const int t0 = warp*32 + pass*4;
        const float* xr = x + (size_t)(b*S_ + blk*256 + t0)*D_;

        ull y2[4][2][2];
        #pragma unroll
        for (int r = 0; r < 4; r++)
            #pragma unroll
            for (int j = 0; j < 2; j++){
                int d = d0 + 128*j;
                float4 xv = *(const float4*)(xr + r*D_ + d);
                ulonglong2 xp = *(ulonglong2*)&xv;
                ulonglong2 dv = *(const ulonglong2*)(sDv + d);
                y2[r][j][0] = mul2(xp.x, dv.x);
                y2[r][j][1] = mul2(xp.y, dv.y);
            }

        #pragma unroll
        for (int n = 0; n < 16; n++){
            float4 h4 = *(const float4*)(shn + n*260 + t0);    // broadcast
            ull ha = pack2(h4.x), hb = pack2(h4.y), hc = pack2(h4.z), hd = pack2(h4.w);
            ulonglong2 c0 = *(const ulonglong2*)(sC + n*260 + d0);
            ulonglong2 c1 = *(const ulonglong2*)(sC + n*260 + d0 + 128);
            fma2(y2[0][0][0], ha, c0.x); fma2(y2[0][0][1], ha, c0.y);
            fma2(y2[0][1][0], ha, c1.x); fma2(y2[0][1][1], ha, c1.y);
            fma2(y2[1][0][0], hb, c0.x); fma2(y2[1][0][1], hb, c0.y);
            fma2(y2[1][1][0], hb, c1.x); fma2(y2[1][1][1], hb, c1.y);
            fma2(y2[2][0][0], hc, c0.x); fma2(y2[2][0][1], hc, c0.y);
            fma2(y2[2][1][0], hc, c1.x); fma2(y2[2][1][1], hc, c1.y);
            fma2(y2[3][0][0], hd, c0.x); fma2(y2[3][0][1], hd, c0.y);
            fma2(y2[3][1][0], hd, c1.x); fma2(y2[3][1][1], hd, c1.y);
        }

        float* og = out + (size_t)(b*S_ + blk*256 + t0)*D_;
        #pragma unroll
        for (int r = 0; r < 4; r++){
            float yv[8];
            float s = 0.f, s2 = 0.f;
            #pragma unroll
            for (int j = 0; j < 2; j++)
                #pragma unroll
                for (int p2 = 0; p2 < 2; p2++){
                    float lo, hi;
                    unpk(lo, hi, y2[r][j][p2]);
                    lo = fminf(fmaxf(lo, -10.f), 10.f);
                    hi = fminf(fmaxf(hi, -10.f), 10.f);
                    yv[j*4 + p2*2]     = lo;
                    yv[j*4 + p2*2 + 1] = hi;
                    s += lo + hi;
                    s2 = fmaf(lo, lo, s2);
                    s2 = fmaf(hi, hi, s2);
                }
            #pragma unroll
            for (int o = 16; o; o >>= 1){
                s  += __shfl_xor_sync(0xffffffffu, s,  o);
                s2 += __shfl_xor_sync(0xffffffffu, s2, o);
            }
            float mu   = s * (1.f/256.f);
            float var  = fmaf(s2, 1.f/256.f, -mu*mu);
            float rinv = rsqrtf(var + LN_EPS);
            #pragma unroll
            for (int j = 0; j < 2; j++){
                int d = d0 + 128*j;
                float4 gg = *(const float4*)(sg + d);
                float4 bb = *(const float4*)(sb + d);
                float4 o4;
                o4.x = fmaf((yv[j*4+0]-mu)*rinv, gg.x, bb.x);
                o4.y = fmaf((yv[j*4+1]-mu)*rinv, gg.y, bb.y);
                o4.z = fmaf((yv[j*4+2]-mu)*rinv, gg.z, bb.z);
                o4.w = fmaf((yv[j*4+3]-mu)*rinv, gg.w, bb.w);
                *(float4*)(og + r*D_ + d) = o4;
            }
        }
    }
}

// ---------------------------------------------------------------------------
extern "C" void kernel_launch(void* const* d_in, const int* in_sizes, int n_in,
                              void* d_out, int out_size){
    const float* x     = (const float*)d_in[0];
    const float* A     = (const float*)d_in[1];
    const float* Bm    = (const float*)d_in[2];
    const float* Cm    = (const float*)d_in[3];
    const float* Dv    = (const float*)d_in[4];
    const float* gamma = (const float*)d_in[5];
    const float* beta  = (const float*)d_in[6];
    float* out = (float*)d_out;

    size_t smem = (size_t)(5120 + 5120 + 4160 + 5120) * sizeof(float); // 78080 B
    cudaFuncSetAttribute(fused, cudaFuncAttributeMaxDynamicSharedMemorySize, (int)smem);

    dim3 grid(S_/256, B_);   // 16 x 16 = 256 blocks; 2/SM -> all co-resident
    fused<<<grid, 256, smem>>>(x, A, Bm, Cm, Dv, gamma, beta, out);
}